// round 2
// baseline (speedup 1.0000x reference)
#include <cuda_runtime.h>
#include <math_constants.h>

// Problem constants
constexpr int BB   = 2;
constexpr int SS   = 2048;
constexpr int DM   = 1024;
constexpr int HH   = 16;
constexpr int DH   = 64;
constexpr int MROW = BB * SS;   // 4096

// Scratch (device globals: allocation-free)
__device__ float g_Q[BB * HH * SS * DH];   // [B,H,S,Dh]
__device__ float g_K[BB * HH * SS * DH];
__device__ float g_V[BB * HH * SS * DH];
__device__ float g_AO[MROW * DM];          // attention output, [B*S, D]

// ---------------------------------------------------------------------------
// GEMM: out = X @ W^T + bias.  X:[M,K] row-major, W:[N,K] row-major.
// 64x64 tile, TK=16, 256 threads, 4x4 microtile per thread.
// SCATTER=true writes to [B,H,S,Dh] layout; else plain [M,N].
// ---------------------------------------------------------------------------
template <bool SCATTER>
__global__ void __launch_bounds__(256) gemm64(const float* __restrict__ X,
                                              const float* __restrict__ W,
                                              const float* __restrict__ bias,
                                              float* __restrict__ out) {
    __shared__ float Xs[16 * 64];   // k-major: Xs[k][m]
    __shared__ float Ws[16 * 64];   // k-major: Ws[k][n]

    const int tid = threadIdx.x;
    const int tx  = tid & 15;       // column group
    const int ty  = tid >> 4;       // row group
    const int lm  = tid & 63;       // load row within tile
    const int lk  = (tid >> 6) << 2;// load k offset (0,4,8,12)
    const int m0  = blockIdx.y << 6;
    const int n0  = blockIdx.x << 6;

    const float* Xp = X + (size_t)(m0 + lm) * DM + lk;
    const float* Wp = W + (size_t)(n0 + lm) * DM + lk;

    float acc[4][4] = {};

    for (int k0 = 0; k0 < DM; k0 += 16) {
        float4 xv = *reinterpret_cast<const float4*>(Xp + k0);
        float4 wv = *reinterpret_cast<const float4*>(Wp + k0);
        __syncthreads();   // protect previous compute phase
        Xs[(lk + 0) * 64 + lm] = xv.x;
        Xs[(lk + 1) * 64 + lm] = xv.y;
        Xs[(lk + 2) * 64 + lm] = xv.z;
        Xs[(lk + 3) * 64 + lm] = xv.w;
        Ws[(lk + 0) * 64 + lm] = wv.x;
        Ws[(lk + 1) * 64 + lm] = wv.y;
        Ws[(lk + 2) * 64 + lm] = wv.z;
        Ws[(lk + 3) * 64 + lm] = wv.w;
        __syncthreads();
#pragma unroll
        for (int kk = 0; kk < 16; kk++) {
            float a[4], b[4];
            *reinterpret_cast<float4*>(a) =
                *reinterpret_cast<const float4*>(&Xs[kk * 64 + ty * 4]);
            *reinterpret_cast<float4*>(b) =
                *reinterpret_cast<const float4*>(&Ws[kk * 64 + tx * 4]);
#pragma unroll
            for (int r = 0; r < 4; r++)
#pragma unroll
                for (int c = 0; c < 4; c++)
                    acc[r][c] = fmaf(a[r], b[c], acc[r][c]);
        }
    }

#pragma unroll
    for (int r = 0; r < 4; r++) {
        const int m = m0 + ty * 4 + r;
#pragma unroll
        for (int c = 0; c < 4; c++) {
            const int n = n0 + tx * 4 + c;
            const float v = acc[r][c] + bias[n];
            if (SCATTER) {
                const int b_ = m >> 11;        // m / S (S=2048)
                const int s_ = m & (SS - 1);
                const int h_ = n >> 6;         // n / DH
                const int d_ = n & (DH - 1);
                out[(((size_t)b_ * HH + h_) * SS + s_) * DH + d_] = v;
            } else {
                out[(size_t)m * DM + n] = v;
            }
        }
    }
}

// ---------------------------------------------------------------------------
// Causal flash attention over [B,H,S,Dh].  One block = one (b,h) x 64-query
// tile.  fp32, online softmax via exp2f.  K smem buffer is reused for P
// (XOR swizzle keeps banks clean); V stored with float4-granular XOR swizzle.
// Each 64x64 tile is loaded by 256 threads x 4 float4 chunks (full 64 depth).
// ---------------------------------------------------------------------------
__global__ void __launch_bounds__(256) attn64(const float* __restrict__ Q,
                                              const float* __restrict__ K,
                                              const float* __restrict__ V,
                                              float* __restrict__ out) {
    __shared__ float Qs[64 * 64];    // d-major: Qs[d][i]
    __shared__ float KPs[64 * 64];   // K tile d-major: KPs[d][j]; reused as P
    __shared__ float Vs[64 * 64];    // j-major, float4-swizzled

    const int tid = threadIdx.x;
    const int tx  = tid & 15;
    const int ty  = tid >> 4;
    const int lm  = tid & 63;        // tile row handled by this thread
    const int dk  = (tid >> 6) << 4; // base d-chunk: 0,16,32,48

    const int q0 = blockIdx.x << 6;
    const int bh = blockIdx.y;

    const float* Qb = Q + (size_t)bh * SS * DH;
    const float* Kb = K + (size_t)bh * SS * DH;
    const float* Vb = V + (size_t)bh * SS * DH;

    // Load Q tile (d-major): 4 float4 chunks per thread -> all 64 d columns
#pragma unroll
    for (int c = 0; c < 4; c++) {
        const int d0 = dk + c * 4;
        float4 qv = *reinterpret_cast<const float4*>(Qb + (size_t)(q0 + lm) * DH + d0);
        Qs[(d0 + 0) * 64 + lm] = qv.x;
        Qs[(d0 + 1) * 64 + lm] = qv.y;
        Qs[(d0 + 2) * 64 + lm] = qv.z;
        Qs[(d0 + 3) * 64 + lm] = qv.w;
    }

    float mi[4], li[4], o[4][4];
#pragma unroll
    for (int r = 0; r < 4; r++) {
        mi[r] = -CUDART_INF_F;
        li[r] = 0.0f;
#pragma unroll
        for (int c = 0; c < 4; c++) o[r][c] = 0.0f;
    }

    const int   ntiles    = (q0 >> 6) + 1;                    // causal
    const float sc_log2e  = 0.125f * 1.4426950408889634f;     // 1/sqrt(64) * log2(e)

    for (int t = 0; t < ntiles; t++) {
        const int j0 = t << 6;
        __syncthreads();   // (A) prev PV finished with KPs/Vs
#pragma unroll
        for (int c = 0; c < 4; c++) {
            const int d0 = dk + c * 4;
            float4 kv = *reinterpret_cast<const float4*>(Kb + (size_t)(j0 + lm) * DH + d0);
            KPs[(d0 + 0) * 64 + lm] = kv.x;
            KPs[(d0 + 1) * 64 + lm] = kv.y;
            KPs[(d0 + 2) * 64 + lm] = kv.z;
            KPs[(d0 + 3) * 64 + lm] = kv.w;
            float4 vv = *reinterpret_cast<const float4*>(Vb + (size_t)(j0 + lm) * DH + d0);
            const int g  = d0 >> 2;                 // float4 group 0..15
            const int c4 = g ^ (lm & 15);
            *reinterpret_cast<float4*>(&Vs[lm * 64 + c4 * 4]) = vv;
        }
        __syncthreads();   // (B) tiles ready

        // Scores: z = (Q K^T) * scale * log2e
        float z[4][4] = {};
#pragma unroll 4
        for (int d = 0; d < 64; d++) {
            float a[4], b[4];
            const float* qrow = &Qs[d * 64 + ty * 4];
            a[0] = qrow[0]; a[1] = qrow[1]; a[2] = qrow[2]; a[3] = qrow[3];
            *reinterpret_cast<float4*>(b) =
                *reinterpret_cast<const float4*>(&KPs[d * 64 + tx * 4]);
#pragma unroll
            for (int r = 0; r < 4; r++)
#pragma unroll
                for (int c = 0; c < 4; c++)
                    z[r][c] = fmaf(a[r], b[c], z[r][c]);
        }
#pragma unroll
        for (int r = 0; r < 4; r++)
#pragma unroll
            for (int c = 0; c < 4; c++)
                z[r][c] *= sc_log2e;

        // Causal mask (only the diagonal tile can have masked entries)
        if (t == ntiles - 1) {
#pragma unroll
            for (int r = 0; r < 4; r++)
#pragma unroll
                for (int c = 0; c < 4; c++)
                    if (j0 + tx * 4 + c > q0 + ty * 4 + r)
                        z[r][c] = -CUDART_INF_F;
        }

        // Row max across 16 lanes sharing the same ty
        float tm[4];
#pragma unroll
        for (int r = 0; r < 4; r++) {
            tm[r] = fmaxf(fmaxf(z[r][0], z[r][1]), fmaxf(z[r][2], z[r][3]));
#pragma unroll
            for (int off = 8; off >= 1; off >>= 1)
                tm[r] = fmaxf(tm[r], __shfl_xor_sync(0xffffffffu, tm[r], off));
        }

        // Online softmax update
        float p[4][4], rs[4];
#pragma unroll
        for (int r = 0; r < 4; r++) {
            const float mn = fmaxf(mi[r], tm[r]);
            const float al = exp2f(mi[r] - mn);
            mi[r] = mn;
            li[r] *= al;
            rs[r] = 0.0f;
#pragma unroll
            for (int c = 0; c < 4; c++) {
                p[r][c] = exp2f(z[r][c] - mn);
                rs[r]  += p[r][c];
                o[r][c] *= al;
            }
#pragma unroll
            for (int off = 8; off >= 1; off >>= 1)
                rs[r] += __shfl_xor_sync(0xffffffffu, rs[r], off);
            li[r] += rs[r];
        }

        __syncthreads();   // (C) all done reading KPs (K)
        // Write P into KPs, j-major with XOR column swizzle
#pragma unroll
        for (int c = 0; c < 4; c++) {
            const int j = tx * 4 + c;
#pragma unroll
            for (int r = 0; r < 4; r++) {
                const int i = ty * 4 + r;
                KPs[j * 64 + ((i + j) & 63)] = p[r][c];
            }
        }
        __syncthreads();   // (D) P ready

        // O += P @ V
#pragma unroll 4
        for (int j = 0; j < 64; j++) {
            float a[4], b[4];
#pragma unroll
            for (int r = 0; r < 4; r++)
                a[r] = KPs[j * 64 + ((ty * 4 + r + j) & 63)];
            const int c4 = tx ^ (j & 15);
            *reinterpret_cast<float4*>(b) =
                *reinterpret_cast<const float4*>(&Vs[j * 64 + c4 * 4]);
#pragma unroll
            for (int r = 0; r < 4; r++)
#pragma unroll
                for (int c = 0; c < 4; c++)
                    o[r][c] = fmaf(a[r], b[c], o[r][c]);
        }
    }

    // Epilogue: normalize and write to [B*S, D] layout (heads re-interleaved)
    const int b_ = bh >> 4;        // bh / H
    const int h_ = bh & (HH - 1);
#pragma unroll
    for (int r = 0; r < 4; r++) {
        const float inv = 1.0f / li[r];
        const int row = q0 + ty * 4 + r;
        float4 v;
        v.x = o[r][0] * inv;
        v.y = o[r][1] * inv;
        v.z = o[r][2] * inv;
        v.w = o[r][3] * inv;
        *reinterpret_cast<float4*>(out + ((size_t)(b_ * SS + row)) * DM + h_ * DH + tx * 4) = v;
    }
}

// ---------------------------------------------------------------------------
extern "C" void kernel_launch(void* const* d_in, const int* in_sizes, int n_in,
                              void* d_out, int out_size) {
    (void)in_sizes; (void)n_in; (void)out_size;
    const float* q    = (const float*)d_in[0];
    const float* k    = (const float*)d_in[1];
    const float* v    = (const float*)d_in[2];
    const float* wq_w = (const float*)d_in[3];
    const float* wq_b = (const float*)d_in[4];
    const float* wk_w = (const float*)d_in[5];
    const float* wk_b = (const float*)d_in[6];
    const float* wv_w = (const float*)d_in[7];
    const float* wv_b = (const float*)d_in[8];
    const float* wo_w = (const float*)d_in[9];
    const float* wo_b = (const float*)d_in[10];
    float* out = (float*)d_out;

    float *gQ, *gK, *gV, *gAO;
    cudaGetSymbolAddress((void**)&gQ,  g_Q);
    cudaGetSymbolAddress((void**)&gK,  g_K);
    cudaGetSymbolAddress((void**)&gV,  g_V);
    cudaGetSymbolAddress((void**)&gAO, g_AO);

    dim3 ggrid(DM / 64, MROW / 64);          // (16, 64)
    gemm64<true><<<ggrid, 256>>>(q, wq_w, wq_b, gQ);
    gemm64<true><<<ggrid, 256>>>(k, wk_w, wk_b, gK);
    gemm64<true><<<ggrid, 256>>>(v, wv_w, wv_b, gV);

    dim3 agrid(SS / 64, BB * HH);            // (32, 32)
    attn64<<<agrid, 256>>>(gQ, gK, gV, gAO);

    gemm64<false><<<ggrid, 256>>>(gAO, wo_w, wo_b, out);
}

// round 4
// speedup vs baseline: 1.7597x; 1.7597x over previous
#include <cuda_runtime.h>
#include <cuda_bf16.h>
#include <math_constants.h>
#include <cstdint>

// Problem constants
constexpr int BB   = 2;
constexpr int SS   = 2048;
constexpr int DM   = 1024;
constexpr int HH   = 16;
constexpr int DH   = 64;
constexpr int MROW = BB * SS;   // 4096

// ---------------------------------------------------------------------------
// Scratch (device globals: allocation-free)
// ---------------------------------------------------------------------------
__device__ float g_Q[BB * HH * SS * DH];   // [B,H,S,Dh] fp32 (attn input)
__device__ float g_K[BB * HH * SS * DH];
__device__ float g_V[BB * HH * SS * DH];
__device__ float g_AO[MROW * DM];          // attention output fp32

// bf16 hi/lo split buffers
__device__ __nv_bfloat16 g_xq_hi[MROW * DM], g_xq_lo[MROW * DM];
__device__ __nv_bfloat16 g_xk_hi[MROW * DM], g_xk_lo[MROW * DM];
__device__ __nv_bfloat16 g_xv_hi[MROW * DM], g_xv_lo[MROW * DM];
__device__ __nv_bfloat16 g_wq_hi[DM * DM],  g_wq_lo[DM * DM];
__device__ __nv_bfloat16 g_wk_hi[DM * DM],  g_wk_lo[DM * DM];
__device__ __nv_bfloat16 g_wv_hi[DM * DM],  g_wv_lo[DM * DM];
__device__ __nv_bfloat16 g_wo_hi[DM * DM],  g_wo_lo[DM * DM];
__device__ __nv_bfloat16 g_ao_hi[MROW * DM], g_ao_lo[MROW * DM];

// ---------------------------------------------------------------------------
// sm_80-level PTX helpers (valid on plain sm_103 target)
// ---------------------------------------------------------------------------
__device__ __forceinline__ uint32_t smem_u32(const void* p) {
    uint32_t a;
    asm("{ .reg .u64 t; cvta.to.shared.u64 t, %1; cvt.u32.u64 %0, t; }" : "=r"(a) : "l"(p));
    return a;
}
__device__ __forceinline__ void cp16(uint32_t saddr, const void* gaddr) {
    asm volatile("cp.async.cg.shared.global [%0], [%1], 16;" :: "r"(saddr), "l"(gaddr));
}
__device__ __forceinline__ void cp_commit() {
    asm volatile("cp.async.commit_group;" ::: "memory");
}
template <int N>
__device__ __forceinline__ void cp_wait() {
    asm volatile("cp.async.wait_group %0;" :: "n"(N) : "memory");
}
__device__ __forceinline__ void ldsm4(uint32_t* r, uint32_t addr) {
    asm volatile("ldmatrix.sync.aligned.m8n8.x4.shared.b16 {%0,%1,%2,%3}, [%4];"
                 : "=r"(r[0]), "=r"(r[1]), "=r"(r[2]), "=r"(r[3]) : "r"(addr));
}
__device__ __forceinline__ void ldsm2(uint32_t* r, uint32_t addr) {
    asm volatile("ldmatrix.sync.aligned.m8n8.x2.shared.b16 {%0,%1}, [%2];"
                 : "=r"(r[0]), "=r"(r[1]) : "r"(addr));
}
__device__ __forceinline__ void mma16816(float* c, const uint32_t* a, const uint32_t* b) {
    asm volatile(
        "mma.sync.aligned.m16n8k16.row.col.f32.bf16.bf16.f32 "
        "{%0,%1,%2,%3}, {%4,%5,%6,%7}, {%8,%9}, {%0,%1,%2,%3};"
        : "+f"(c[0]), "+f"(c[1]), "+f"(c[2]), "+f"(c[3])
        : "r"(a[0]), "r"(a[1]), "r"(a[2]), "r"(a[3]), "r"(b[0]), "r"(b[1]));
}

// ---------------------------------------------------------------------------
// Convert fp32 -> bf16 hi/lo split
// ---------------------------------------------------------------------------
__global__ void __launch_bounds__(256) cvt_split(const float* __restrict__ src,
                                                 __nv_bfloat16* __restrict__ hi,
                                                 __nv_bfloat16* __restrict__ lo,
                                                 int n) {
    int i = (blockIdx.x * 256 + threadIdx.x) * 4;
    if (i >= n) return;
    float4 v = *reinterpret_cast<const float4*>(src + i);
    __nv_bfloat16 h0 = __float2bfloat16(v.x);
    __nv_bfloat16 h1 = __float2bfloat16(v.y);
    __nv_bfloat16 h2 = __float2bfloat16(v.z);
    __nv_bfloat16 h3 = __float2bfloat16(v.w);
    __nv_bfloat16 l0 = __float2bfloat16(v.x - __bfloat162float(h0));
    __nv_bfloat16 l1 = __float2bfloat16(v.y - __bfloat162float(h1));
    __nv_bfloat16 l2 = __float2bfloat16(v.z - __bfloat162float(h2));
    __nv_bfloat16 l3 = __float2bfloat16(v.w - __bfloat162float(h3));
    reinterpret_cast<__nv_bfloat162*>(hi + i)[0] = __halves2bfloat162(h0, h1);
    reinterpret_cast<__nv_bfloat162*>(hi + i)[1] = __halves2bfloat162(h2, h3);
    reinterpret_cast<__nv_bfloat162*>(lo + i)[0] = __halves2bfloat162(l0, l1);
    reinterpret_cast<__nv_bfloat162*>(lo + i)[1] = __halves2bfloat162(l2, l3);
}

// ---------------------------------------------------------------------------
// mma.sync GEMM: out[M,N] = A @ B^T + bias
// A:[M,K] = Ahi+Alo (bf16), B:[N,K] = Bhi+Blo (bf16), fp32 accumulate.
// 3-term split: Ahi*Bhi + Alo*Bhi + Ahi*Blo.
// CTA tile 128x128, warp tile 64x32, K-stage 64, cp.async double buffer.
// ---------------------------------------------------------------------------
constexpr int TM = 128, TN = 128, TK = 64;
constexpr int NSTAGE = DM / TK;               // 16
constexpr int ROWB   = 144;                   // padded row stride bytes (64 bf16 -> 144B)
constexpr int TILE_B = 128 * ROWB;            // 18432
constexpr int BUF_B  = 4 * TILE_B;            // Ahi,Alo,Bhi,Blo = 73728
constexpr int GEMM_SMEM = 2 * BUF_B;          // 147456

template <bool SCATTER>
__global__ void __launch_bounds__(256, 1) gemm_mma(const __nv_bfloat16* __restrict__ Ahi,
                                                   const __nv_bfloat16* __restrict__ Alo,
                                                   const __nv_bfloat16* __restrict__ Bhi,
                                                   const __nv_bfloat16* __restrict__ Blo,
                                                   const float* __restrict__ bias,
                                                   float* __restrict__ out) {
    extern __shared__ __align__(128) char smem[];
    const uint32_t sb = smem_u32(smem);
    const int tid = threadIdx.x;
    const int wid = tid >> 5;
    const int lid = tid & 31;
    const int wm  = wid >> 2;        // 0..1 (warp row)
    const int wn  = wid & 3;         // 0..3 (warp col)
    const int m0  = blockIdx.y * TM;
    const int n0  = blockIdx.x * TN;

    const __nv_bfloat16* gsrc[4] = {Ahi, Alo, Bhi, Blo};
    const int gbase[4] = {m0, m0, n0, n0};

    // Issue one K-stage (4 tiles of 128 rows x 64 bf16) via cp.async
    auto issue_stage = [&](int s) {
        const int b = s & 1;
        const int k0 = s * TK;
        const uint32_t sbase = sb + b * BUF_B;
#pragma unroll
        for (int t = 0; t < 4; t++) {
            const __nv_bfloat16* src = gsrc[t];
            const int rb = gbase[t];
#pragma unroll
            for (int i = 0; i < 4; i++) {
                const int idx = tid + i * 256;      // 0..1023
                const int row = idx >> 3;
                const int c   = idx & 7;
                const void* g = src + (size_t)(rb + row) * DM + k0 + c * 8;
                cp16(sbase + t * TILE_B + row * ROWB + c * 16, g);
            }
        }
        cp_commit();
    };

    issue_stage(0);
    issue_stage(1);

    float acc[4][4][4] = {};   // [mi][ni][4]

    // per-lane ldmatrix address components
    const int aRowIn = (lid & 7) + 8 * ((lid >> 3) & 1);   // row within 16-row atom
    const int aKc    = ((lid >> 4) & 1) * 16;              // 0 or 16 bytes (k half)
    const int bNIn   = (lid & 7);
    const int bKc    = ((lid >> 3) & 1) * 16;

    for (int s = 0; s < NSTAGE; s++) {
        if (s == NSTAGE - 1) cp_wait<0>(); else cp_wait<1>();
        __syncthreads();

        const uint32_t sbase = sb + (s & 1) * BUF_B;
        const uint32_t Ah = sbase;
        const uint32_t Al = sbase + TILE_B;
        const uint32_t Bh = sbase + 2 * TILE_B;
        const uint32_t Bl = sbase + 3 * TILE_B;

#pragma unroll
        for (int ks = 0; ks < 4; ks++) {
            const int kb = ks * 32;    // byte offset of 16-k chunk (16 bf16 = 32B)
            uint32_t bh[4][2], bl[4][2];
#pragma unroll
            for (int ni = 0; ni < 4; ni++) {
                const uint32_t boff = (uint32_t)((wn * 32 + ni * 8 + bNIn) * ROWB + kb + bKc);
                ldsm2(bh[ni], Bh + boff);
                ldsm2(bl[ni], Bl + boff);
            }
#pragma unroll
            for (int mi = 0; mi < 4; mi++) {
                uint32_t ah[4], al[4];
                const uint32_t aoff = (uint32_t)((wm * 64 + mi * 16 + aRowIn) * ROWB + kb + aKc);
                ldsm4(ah, Ah + aoff);
                ldsm4(al, Al + aoff);
#pragma unroll
                for (int ni = 0; ni < 4; ni++) {
                    mma16816(acc[mi][ni], ah, bh[ni]);
                    mma16816(acc[mi][ni], al, bh[ni]);
                    mma16816(acc[mi][ni], ah, bl[ni]);
                }
            }
        }
        __syncthreads();
        if (s + 2 < NSTAGE) issue_stage(s + 2);
    }

    // Epilogue
    const int qr = lid >> 2;          // 0..7
    const int qc = (lid & 3) * 2;     // 0,2,4,6
#pragma unroll
    for (int mi = 0; mi < 4; mi++) {
#pragma unroll
        for (int ni = 0; ni < 4; ni++) {
            const int n = n0 + wn * 32 + ni * 8 + qc;
            const float2 bv = *reinterpret_cast<const float2*>(bias + n);
#pragma unroll
            for (int half = 0; half < 2; half++) {
                const int m = m0 + wm * 64 + mi * 16 + qr + half * 8;
                float2 v;
                v.x = acc[mi][ni][half * 2 + 0] + bv.x;
                v.y = acc[mi][ni][half * 2 + 1] + bv.y;
                float* po;
                if (SCATTER) {
                    const int b_ = m >> 11;
                    const int s_ = m & (SS - 1);
                    const int h_ = n >> 6;
                    const int d_ = n & (DH - 1);
                    po = out + (((size_t)b_ * HH + h_) * SS + s_) * DH + d_;
                } else {
                    po = out + (size_t)m * DM + n;
                }
                *reinterpret_cast<float2*>(po) = v;
            }
        }
    }
}

// ---------------------------------------------------------------------------
// Causal flash attention (scalar fp32) — unchanged from passing round-2 kernel
// ---------------------------------------------------------------------------
__global__ void __launch_bounds__(256) attn64(const float* __restrict__ Q,
                                              const float* __restrict__ K,
                                              const float* __restrict__ V,
                                              float* __restrict__ out) {
    __shared__ float Qs[64 * 64];
    __shared__ float KPs[64 * 64];
    __shared__ float Vs[64 * 64];

    const int tid = threadIdx.x;
    const int tx  = tid & 15;
    const int ty  = tid >> 4;
    const int lm  = tid & 63;
    const int dk  = (tid >> 6) << 4;

    const int q0 = blockIdx.x << 6;
    const int bh = blockIdx.y;

    const float* Qb = Q + (size_t)bh * SS * DH;
    const float* Kb = K + (size_t)bh * SS * DH;
    const float* Vb = V + (size_t)bh * SS * DH;

#pragma unroll
    for (int c = 0; c < 4; c++) {
        const int d0 = dk + c * 4;
        float4 qv = *reinterpret_cast<const float4*>(Qb + (size_t)(q0 + lm) * DH + d0);
        Qs[(d0 + 0) * 64 + lm] = qv.x;
        Qs[(d0 + 1) * 64 + lm] = qv.y;
        Qs[(d0 + 2) * 64 + lm] = qv.z;
        Qs[(d0 + 3) * 64 + lm] = qv.w;
    }

    float mi[4], li[4], o[4][4];
#pragma unroll
    for (int r = 0; r < 4; r++) {
        mi[r] = -CUDART_INF_F;
        li[r] = 0.0f;
#pragma unroll
        for (int c = 0; c < 4; c++) o[r][c] = 0.0f;
    }

    const int   ntiles   = (q0 >> 6) + 1;
    const float sc_log2e = 0.125f * 1.4426950408889634f;

    for (int t = 0; t < ntiles; t++) {
        const int j0 = t << 6;
        __syncthreads();
#pragma unroll
        for (int c = 0; c < 4; c++) {
            const int d0 = dk + c * 4;
            float4 kv = *reinterpret_cast<const float4*>(Kb + (size_t)(j0 + lm) * DH + d0);
            KPs[(d0 + 0) * 64 + lm] = kv.x;
            KPs[(d0 + 1) * 64 + lm] = kv.y;
            KPs[(d0 + 2) * 64 + lm] = kv.z;
            KPs[(d0 + 3) * 64 + lm] = kv.w;
            float4 vv = *reinterpret_cast<const float4*>(Vb + (size_t)(j0 + lm) * DH + d0);
            const int g  = d0 >> 2;
            const int c4 = g ^ (lm & 15);
            *reinterpret_cast<float4*>(&Vs[lm * 64 + c4 * 4]) = vv;
        }
        __syncthreads();

        float z[4][4] = {};
#pragma unroll 4
        for (int d = 0; d < 64; d++) {
            float a[4], b[4];
            const float* qrow = &Qs[d * 64 + ty * 4];
            a[0] = qrow[0]; a[1] = qrow[1]; a[2] = qrow[2]; a[3] = qrow[3];
            *reinterpret_cast<float4*>(b) =
                *reinterpret_cast<const float4*>(&KPs[d * 64 + tx * 4]);
#pragma unroll
            for (int r = 0; r < 4; r++)
#pragma unroll
                for (int c = 0; c < 4; c++)
                    z[r][c] = fmaf(a[r], b[c], z[r][c]);
        }
#pragma unroll
        for (int r = 0; r < 4; r++)
#pragma unroll
            for (int c = 0; c < 4; c++)
                z[r][c] *= sc_log2e;

        if (t == ntiles - 1) {
#pragma unroll
            for (int r = 0; r < 4; r++)
#pragma unroll
                for (int c = 0; c < 4; c++)
                    if (j0 + tx * 4 + c > q0 + ty * 4 + r)
                        z[r][c] = -CUDART_INF_F;
        }

        float tm[4];
#pragma unroll
        for (int r = 0; r < 4; r++) {
            tm[r] = fmaxf(fmaxf(z[r][0], z[r][1]), fmaxf(z[r][2], z[r][3]));
#pragma unroll
            for (int off = 8; off >= 1; off >>= 1)
                tm[r] = fmaxf(tm[r], __shfl_xor_sync(0xffffffffu, tm[r], off));
        }

        float p[4][4], rs[4];
#pragma unroll
        for (int r = 0; r < 4; r++) {
            const float mn = fmaxf(mi[r], tm[r]);
            const float al = exp2f(mi[r] - mn);
            mi[r] = mn;
            li[r] *= al;
            rs[r] = 0.0f;
#pragma unroll
            for (int c = 0; c < 4; c++) {
                p[r][c] = exp2f(z[r][c] - mn);
                rs[r]  += p[r][c];
                o[r][c] *= al;
            }
#pragma unroll
            for (int off = 8; off >= 1; off >>= 1)
                rs[r] += __shfl_xor_sync(0xffffffffu, rs[r], off);
            li[r] += rs[r];
        }

        __syncthreads();
#pragma unroll
        for (int c = 0; c < 4; c++) {
            const int j = tx * 4 + c;
#pragma unroll
            for (int r = 0; r < 4; r++) {
                const int i = ty * 4 + r;
                KPs[j * 64 + ((i + j) & 63)] = p[r][c];
            }
        }
        __syncthreads();

#pragma unroll 4
        for (int j = 0; j < 64; j++) {
            float a[4], b[4];
#pragma unroll
            for (int r = 0; r < 4; r++)
                a[r] = KPs[j * 64 + ((ty * 4 + r + j) & 63)];
            const int c4 = tx ^ (j & 15);
            *reinterpret_cast<float4*>(b) =
                *reinterpret_cast<const float4*>(&Vs[j * 64 + c4 * 4]);
#pragma unroll
            for (int r = 0; r < 4; r++)
#pragma unroll
                for (int c = 0; c < 4; c++)
                    o[r][c] = fmaf(a[r], b[c], o[r][c]);
        }
    }

    const int b_ = bh >> 4;
    const int h_ = bh & (HH - 1);
#pragma unroll
    for (int r = 0; r < 4; r++) {
        const float inv = 1.0f / li[r];
        const int row = q0 + ty * 4 + r;
        float4 v;
        v.x = o[r][0] * inv;
        v.y = o[r][1] * inv;
        v.z = o[r][2] * inv;
        v.w = o[r][3] * inv;
        *reinterpret_cast<float4*>(out + ((size_t)(b_ * SS + row)) * DM + h_ * DH + tx * 4) = v;
    }
}

// ---------------------------------------------------------------------------
extern "C" void kernel_launch(void* const* d_in, const int* in_sizes, int n_in,
                              void* d_out, int out_size) {
    (void)in_sizes; (void)n_in; (void)out_size;
    const float* q    = (const float*)d_in[0];
    const float* k    = (const float*)d_in[1];
    const float* v    = (const float*)d_in[2];
    const float* wq_w = (const float*)d_in[3];
    const float* wq_b = (const float*)d_in[4];
    const float* wk_w = (const float*)d_in[5];
    const float* wk_b = (const float*)d_in[6];
    const float* wv_w = (const float*)d_in[7];
    const float* wv_b = (const float*)d_in[8];
    const float* wo_w = (const float*)d_in[9];
    const float* wo_b = (const float*)d_in[10];
    float* out = (float*)d_out;

    float *gQ, *gK, *gV, *gAO;
    cudaGetSymbolAddress((void**)&gQ,  g_Q);
    cudaGetSymbolAddress((void**)&gK,  g_K);
    cudaGetSymbolAddress((void**)&gV,  g_V);
    cudaGetSymbolAddress((void**)&gAO, g_AO);

    __nv_bfloat16 *xqh, *xql, *xkh, *xkl, *xvh, *xvl;
    __nv_bfloat16 *wqh, *wql, *wkh, *wkl, *wvh, *wvl, *woh, *wol, *aoh, *aol;
    cudaGetSymbolAddress((void**)&xqh, g_xq_hi); cudaGetSymbolAddress((void**)&xql, g_xq_lo);
    cudaGetSymbolAddress((void**)&xkh, g_xk_hi); cudaGetSymbolAddress((void**)&xkl, g_xk_lo);
    cudaGetSymbolAddress((void**)&xvh, g_xv_hi); cudaGetSymbolAddress((void**)&xvl, g_xv_lo);
    cudaGetSymbolAddress((void**)&wqh, g_wq_hi); cudaGetSymbolAddress((void**)&wql, g_wq_lo);
    cudaGetSymbolAddress((void**)&wkh, g_wk_hi); cudaGetSymbolAddress((void**)&wkl, g_wk_lo);
    cudaGetSymbolAddress((void**)&wvh, g_wv_hi); cudaGetSymbolAddress((void**)&wvl, g_wv_lo);
    cudaGetSymbolAddress((void**)&woh, g_wo_hi); cudaGetSymbolAddress((void**)&wol, g_wo_lo);
    cudaGetSymbolAddress((void**)&aoh, g_ao_hi); cudaGetSymbolAddress((void**)&aol, g_ao_lo);

    cudaFuncSetAttribute(gemm_mma<true>,  cudaFuncAttributeMaxDynamicSharedMemorySize, GEMM_SMEM);
    cudaFuncSetAttribute(gemm_mma<false>, cudaFuncAttributeMaxDynamicSharedMemorySize, GEMM_SMEM);

    const int NX = MROW * DM;   // 4M
    const int NW = DM * DM;     // 1M
    cvt_split<<<NX / 1024, 256>>>(q, xqh, xql, NX);
    cvt_split<<<NX / 1024, 256>>>(k, xkh, xkl, NX);
    cvt_split<<<NX / 1024, 256>>>(v, xvh, xvl, NX);
    cvt_split<<<NW / 1024, 256>>>(wq_w, wqh, wql, NW);
    cvt_split<<<NW / 1024, 256>>>(wk_w, wkh, wkl, NW);
    cvt_split<<<NW / 1024, 256>>>(wv_w, wvh, wvl, NW);
    cvt_split<<<NW / 1024, 256>>>(wo_w, woh, wol, NW);

    dim3 ggrid(DM / TN, MROW / TM);   // (8, 32)
    gemm_mma<true><<<ggrid, 256, GEMM_SMEM>>>(xqh, xql, wqh, wql, wq_b, gQ);
    gemm_mma<true><<<ggrid, 256, GEMM_SMEM>>>(xkh, xkl, wkh, wkl, wk_b, gK);
    gemm_mma<true><<<ggrid, 256, GEMM_SMEM>>>(xvh, xvl, wvh, wvl, wv_b, gV);

    dim3 agrid(SS / 64, BB * HH);     // (32, 32)
    attn64<<<agrid, 256>>>(gQ, gK, gV, gAO);

    cvt_split<<<NX / 1024, 256>>>(gAO, aoh, aol, NX);
    gemm_mma<false><<<ggrid, 256, GEMM_SMEM>>>(aoh, aol, woh, wol, wo_b, out);
}

// round 5
// speedup vs baseline: 3.6912x; 2.0976x over previous
#include <cuda_runtime.h>
#include <cuda_bf16.h>
#include <math_constants.h>
#include <cstdint>

// Problem constants
constexpr int BB   = 2;
constexpr int SS   = 2048;
constexpr int DM   = 1024;
constexpr int HH   = 16;
constexpr int DH   = 64;
constexpr int MROW = BB * SS;   // 4096

// ---------------------------------------------------------------------------
// Scratch (device globals: allocation-free)
// ---------------------------------------------------------------------------
// bf16 hi/lo split inputs
__device__ __nv_bfloat16 g_xq_hi[MROW * DM], g_xq_lo[MROW * DM];
__device__ __nv_bfloat16 g_xk_hi[MROW * DM], g_xk_lo[MROW * DM];
__device__ __nv_bfloat16 g_xv_hi[MROW * DM], g_xv_lo[MROW * DM];
__device__ __nv_bfloat16 g_wq_hi[DM * DM],  g_wq_lo[DM * DM];
__device__ __nv_bfloat16 g_wk_hi[DM * DM],  g_wk_lo[DM * DM];
__device__ __nv_bfloat16 g_wv_hi[DM * DM],  g_wv_lo[DM * DM];
__device__ __nv_bfloat16 g_wo_hi[DM * DM],  g_wo_lo[DM * DM];
// projected Q/K/V, bf16 hi/lo, [B,H,S,Dh]
__device__ __nv_bfloat16 g_Qh[BB*HH*SS*DH], g_Ql[BB*HH*SS*DH];
__device__ __nv_bfloat16 g_Kh[BB*HH*SS*DH], g_Kl[BB*HH*SS*DH];
__device__ __nv_bfloat16 g_Vh[BB*HH*SS*DH], g_Vl[BB*HH*SS*DH];
// attention output, bf16 hi/lo, [B*S, DM]
__device__ __nv_bfloat16 g_aoh[MROW * DM], g_aol[MROW * DM];

// ---------------------------------------------------------------------------
// sm_80-level PTX helpers (valid on plain sm_103 target)
// ---------------------------------------------------------------------------
__device__ __forceinline__ uint32_t smem_u32(const void* p) {
    uint32_t a;
    asm("{ .reg .u64 t; cvta.to.shared.u64 t, %1; cvt.u32.u64 %0, t; }" : "=r"(a) : "l"(p));
    return a;
}
__device__ __forceinline__ void cp16(uint32_t saddr, const void* gaddr) {
    asm volatile("cp.async.cg.shared.global [%0], [%1], 16;" :: "r"(saddr), "l"(gaddr));
}
__device__ __forceinline__ void cp_commit() {
    asm volatile("cp.async.commit_group;" ::: "memory");
}
template <int N>
__device__ __forceinline__ void cp_wait() {
    asm volatile("cp.async.wait_group %0;" :: "n"(N) : "memory");
}
__device__ __forceinline__ void ldsm4(uint32_t* r, uint32_t addr) {
    asm volatile("ldmatrix.sync.aligned.m8n8.x4.shared.b16 {%0,%1,%2,%3}, [%4];"
                 : "=r"(r[0]), "=r"(r[1]), "=r"(r[2]), "=r"(r[3]) : "r"(addr));
}
__device__ __forceinline__ void ldsm2(uint32_t* r, uint32_t addr) {
    asm volatile("ldmatrix.sync.aligned.m8n8.x2.shared.b16 {%0,%1}, [%2];"
                 : "=r"(r[0]), "=r"(r[1]) : "r"(addr));
}
__device__ __forceinline__ void ldsm2t(uint32_t* r, uint32_t addr) {
    asm volatile("ldmatrix.sync.aligned.m8n8.x2.trans.shared.b16 {%0,%1}, [%2];"
                 : "=r"(r[0]), "=r"(r[1]) : "r"(addr));
}
__device__ __forceinline__ void mma16816(float* c, const uint32_t* a, const uint32_t* b) {
    asm volatile(
        "mma.sync.aligned.m16n8k16.row.col.f32.bf16.bf16.f32 "
        "{%0,%1,%2,%3}, {%4,%5,%6,%7}, {%8,%9}, {%0,%1,%2,%3};"
        : "+f"(c[0]), "+f"(c[1]), "+f"(c[2]), "+f"(c[3])
        : "r"(a[0]), "r"(a[1]), "r"(a[2]), "r"(a[3]), "r"(b[0]), "r"(b[1]));
}
// pack two fp32 into bf16 hi pair + residual lo pair
__device__ __forceinline__ void split2(float a, float b, uint32_t& hi, uint32_t& lo) {
    __nv_bfloat16 ha = __float2bfloat16(a);
    __nv_bfloat16 hb = __float2bfloat16(b);
    __nv_bfloat162 hv; hv.x = ha; hv.y = hb;
    __nv_bfloat162 lv;
    lv.x = __float2bfloat16(a - __bfloat162float(ha));
    lv.y = __float2bfloat16(b - __bfloat162float(hb));
    hi = *reinterpret_cast<uint32_t*>(&hv);
    lo = *reinterpret_cast<uint32_t*>(&lv);
}

// ---------------------------------------------------------------------------
// Convert fp32 -> bf16 hi/lo split
// ---------------------------------------------------------------------------
__global__ void __launch_bounds__(256) cvt_split(const float* __restrict__ src,
                                                 __nv_bfloat16* __restrict__ hi,
                                                 __nv_bfloat16* __restrict__ lo,
                                                 int n) {
    int i = (blockIdx.x * 256 + threadIdx.x) * 4;
    if (i >= n) return;
    float4 v = *reinterpret_cast<const float4*>(src + i);
    uint32_t h0, l0, h1, l1;
    split2(v.x, v.y, h0, l0);
    split2(v.z, v.w, h1, l1);
    reinterpret_cast<uint32_t*>(hi + i)[0] = h0;
    reinterpret_cast<uint32_t*>(hi + i)[1] = h1;
    reinterpret_cast<uint32_t*>(lo + i)[0] = l0;
    reinterpret_cast<uint32_t*>(lo + i)[1] = l1;
}

// ---------------------------------------------------------------------------
// mma.sync GEMM: out = A @ B^T + bias.  3-term bf16 hi/lo split, fp32 accum.
// CTA 128x128, warp 64x32, K-stage 64, cp.async double buffer.
// SCATTER=true: write bf16 hi/lo to [B,H,S,Dh]; else fp32 [M,N].
// ---------------------------------------------------------------------------
constexpr int TM = 128, TN = 128, TK = 64;
constexpr int NSTAGE = DM / TK;               // 16
constexpr int ROWB   = 144;                   // padded row stride bytes
constexpr int TILE_B = 128 * ROWB;            // 18432
constexpr int BUF_B  = 4 * TILE_B;            // 73728
constexpr int GEMM_SMEM = 2 * BUF_B;          // 147456

template <bool SCATTER>
__global__ void __launch_bounds__(256, 1) gemm_mma(const __nv_bfloat16* __restrict__ Ahi,
                                                   const __nv_bfloat16* __restrict__ Alo,
                                                   const __nv_bfloat16* __restrict__ Bhi,
                                                   const __nv_bfloat16* __restrict__ Blo,
                                                   const float* __restrict__ bias,
                                                   float* __restrict__ out,
                                                   __nv_bfloat16* __restrict__ out_hi,
                                                   __nv_bfloat16* __restrict__ out_lo) {
    extern __shared__ __align__(128) char smem[];
    const uint32_t sb = smem_u32(smem);
    const int tid = threadIdx.x;
    const int wid = tid >> 5;
    const int lid = tid & 31;
    const int wm  = wid >> 2;
    const int wn  = wid & 3;
    const int m0  = blockIdx.y * TM;
    const int n0  = blockIdx.x * TN;

    const __nv_bfloat16* gsrc[4] = {Ahi, Alo, Bhi, Blo};
    const int gbase[4] = {m0, m0, n0, n0};

    auto issue_stage = [&](int s) {
        const int b = s & 1;
        const int k0 = s * TK;
        const uint32_t sbase = sb + b * BUF_B;
#pragma unroll
        for (int t = 0; t < 4; t++) {
            const __nv_bfloat16* src = gsrc[t];
            const int rb = gbase[t];
#pragma unroll
            for (int i = 0; i < 4; i++) {
                const int idx = tid + i * 256;
                const int row = idx >> 3;
                const int c   = idx & 7;
                cp16(sbase + t * TILE_B + row * ROWB + c * 16,
                     src + (size_t)(rb + row) * DM + k0 + c * 8);
            }
        }
        cp_commit();
    };

    issue_stage(0);
    issue_stage(1);

    float acc[4][4][4] = {};

    const int aRowIn = (lid & 7) + 8 * ((lid >> 3) & 1);
    const int aKc    = ((lid >> 4) & 1) * 16;
    const int bNIn   = (lid & 7);
    const int bKc    = ((lid >> 3) & 1) * 16;

    for (int s = 0; s < NSTAGE; s++) {
        if (s == NSTAGE - 1) cp_wait<0>(); else cp_wait<1>();
        __syncthreads();

        const uint32_t sbase = sb + (s & 1) * BUF_B;
        const uint32_t Ah = sbase;
        const uint32_t Al = sbase + TILE_B;
        const uint32_t Bh = sbase + 2 * TILE_B;
        const uint32_t Bl = sbase + 3 * TILE_B;

#pragma unroll
        for (int ks = 0; ks < 4; ks++) {
            const int kb = ks * 32;
            uint32_t bh[4][2], bl[4][2];
#pragma unroll
            for (int ni = 0; ni < 4; ni++) {
                const uint32_t boff = (uint32_t)((wn * 32 + ni * 8 + bNIn) * ROWB + kb + bKc);
                ldsm2(bh[ni], Bh + boff);
                ldsm2(bl[ni], Bl + boff);
            }
#pragma unroll
            for (int mi = 0; mi < 4; mi++) {
                uint32_t ah[4], al[4];
                const uint32_t aoff = (uint32_t)((wm * 64 + mi * 16 + aRowIn) * ROWB + kb + aKc);
                ldsm4(ah, Ah + aoff);
                ldsm4(al, Al + aoff);
#pragma unroll
                for (int ni = 0; ni < 4; ni++) {
                    mma16816(acc[mi][ni], ah, bh[ni]);
                    mma16816(acc[mi][ni], al, bh[ni]);
                    mma16816(acc[mi][ni], ah, bl[ni]);
                }
            }
        }
        __syncthreads();
        if (s + 2 < NSTAGE) issue_stage(s + 2);
    }

    // Epilogue
    const int qr = lid >> 2;
    const int qc = (lid & 3) * 2;
#pragma unroll
    for (int mi = 0; mi < 4; mi++) {
#pragma unroll
        for (int ni = 0; ni < 4; ni++) {
            const int n = n0 + wn * 32 + ni * 8 + qc;
            const float2 bv = *reinterpret_cast<const float2*>(bias + n);
#pragma unroll
            for (int half = 0; half < 2; half++) {
                const int m = m0 + wm * 64 + mi * 16 + qr + half * 8;
                const float vx = acc[mi][ni][half * 2 + 0] + bv.x;
                const float vy = acc[mi][ni][half * 2 + 1] + bv.y;
                if (SCATTER) {
                    const int b_ = m >> 11;
                    const int s_ = m & (SS - 1);
                    const int h_ = n >> 6;
                    const int d_ = n & (DH - 1);
                    const size_t o = (((size_t)b_ * HH + h_) * SS + s_) * DH + d_;
                    uint32_t hv, lv;
                    split2(vx, vy, hv, lv);
                    *reinterpret_cast<uint32_t*>(out_hi + o) = hv;
                    *reinterpret_cast<uint32_t*>(out_lo + o) = lv;
                } else {
                    float2 v; v.x = vx; v.y = vy;
                    *reinterpret_cast<float2*>(out + (size_t)m * DM + n) = v;
                }
            }
        }
    }
}

// ---------------------------------------------------------------------------
// mma.sync causal flash attention.
// CTA: 128 queries x one (b,h).  8 warps, warp = 16 q rows x 64 kv cols.
// Scores: 3-term bf16 hi/lo (Qh*Kh + Ql*Kh + Qh*Kl), fp32 accum.
// PV:     3-term with P split in registers (C-frag -> A-frag identity).
// V via ldmatrix.trans.  cp.async double-buffered K/V tiles.
// Output: bf16 hi/lo to [B*S, DM].
// ---------------------------------------------------------------------------
constexpr int AROWB   = 144;
constexpr int TILE_KV = 64 * AROWB;            // 9216
constexpr int STAGE_B = 4 * TILE_KV;           // Kh,Kl,Vh,Vl = 36864
constexpr int QOFF    = 2 * STAGE_B;           // 73728
constexpr int QTILE   = 128 * AROWB;           // 18432
constexpr int ATTN_SMEM = QOFF + 2 * QTILE;    // 110592

__global__ void __launch_bounds__(256, 1) attn_mma(const __nv_bfloat16* __restrict__ Qh_g,
                                                   const __nv_bfloat16* __restrict__ Ql_g,
                                                   const __nv_bfloat16* __restrict__ Kh_g,
                                                   const __nv_bfloat16* __restrict__ Kl_g,
                                                   const __nv_bfloat16* __restrict__ Vh_g,
                                                   const __nv_bfloat16* __restrict__ Vl_g,
                                                   __nv_bfloat16* __restrict__ aoh,
                                                   __nv_bfloat16* __restrict__ aol) {
    extern __shared__ __align__(128) char smem[];
    const uint32_t sb = smem_u32(smem);
    const int tid = threadIdx.x;
    const int w   = tid >> 5;
    const int lid = tid & 31;

    const int q0 = blockIdx.x * 128;
    const int bh = blockIdx.y;
    const size_t bhbase = (size_t)bh * SS;

    const int ntiles = (q0 >> 6) + 2;

    // ---- issue Q + kv stage 0 (group 0), kv stage 1 (group 1) ----
    auto issue_kv = [&](int t) {
        const int j0 = t * 64;
        const uint32_t sbase = sb + (t & 1) * STAGE_B;
        const __nv_bfloat16* srcs[4] = {Kh_g, Kl_g, Vh_g, Vl_g};
#pragma unroll
        for (int a = 0; a < 4; a++) {
#pragma unroll
            for (int i = 0; i < 2; i++) {
                const int idx = tid + i * 256;          // 0..511
                const int row = idx >> 3, c = idx & 7;
                cp16(sbase + a * TILE_KV + row * AROWB + c * 16,
                     srcs[a] + (bhbase + j0 + row) * DH + c * 8);
            }
        }
        cp_commit();
    };

    {   // Q (128 rows x 8 chunks x hi/lo) + kv tile 0 in group 0
        const __nv_bfloat16* qs[2] = {Qh_g, Ql_g};
#pragma unroll
        for (int a = 0; a < 2; a++) {
#pragma unroll
            for (int i = 0; i < 4; i++) {
                const int idx = tid + i * 256;          // 0..1023
                const int row = idx >> 3, c = idx & 7;
                cp16(sb + QOFF + a * QTILE + row * AROWB + c * 16,
                     qs[a] + (bhbase + q0 + row) * DH + c * 8);
            }
        }
        issue_kv(0);   // commits group 0 (Q + kv0)
    }
    if (ntiles > 1) issue_kv(1);

    // fragment index components
    const int aRowIn = (lid & 7) + 8 * ((lid >> 3) & 1);
    const int aKc    = ((lid >> 4) & 1) * 16;

    uint32_t qh[4][4], ql[4][4];
    float O[8][4] = {};
    float mi0 = -CUDART_INF_F, mi1 = -CUDART_INF_F;
    float li0 = 0.0f, li1 = 0.0f;
    const float sc_log2e = 0.125f * 1.4426950408889634f;

    for (int t = 0; t < ntiles; t++) {
        if (t == ntiles - 1) cp_wait<0>(); else cp_wait<1>();
        __syncthreads();

        if (t == 0) {   // Q fragments (group 0 complete)
            const uint32_t qb = sb + QOFF + (uint32_t)((w * 16 + aRowIn) * AROWB + aKc);
#pragma unroll
            for (int kc = 0; kc < 4; kc++) {
                ldsm4(qh[kc], qb + kc * 32);
                ldsm4(ql[kc], qb + QTILE + kc * 32);
            }
        }

        const uint32_t kvb = sb + (t & 1) * STAGE_B;
        const int j0 = t * 64;

        // ---- scores ----
        float z[8][4] = {};
#pragma unroll
        for (int kc = 0; kc < 4; kc++) {
#pragma unroll
            for (int ni = 0; ni < 8; ni++) {
                uint32_t kh[2], kl[2];
                const uint32_t ko = kvb + (uint32_t)((ni * 8 + (lid & 7)) * AROWB
                                                     + kc * 32 + ((lid >> 3) & 1) * 16);
                ldsm2(kh, ko);
                ldsm2(kl, ko + TILE_KV);
                mma16816(z[ni], qh[kc], kh);
                mma16816(z[ni], ql[kc], kh);
                mma16816(z[ni], qh[kc], kl);
            }
        }

        // scale + causal mask
        const int qA = q0 + w * 16 + (lid >> 2);
        const int qB = qA + 8;
        const bool domask = (j0 + 63 > q0 + w * 16);
#pragma unroll
        for (int ni = 0; ni < 8; ni++) {
#pragma unroll
            for (int c = 0; c < 4; c++) z[ni][c] *= sc_log2e;
            if (domask) {
                const int col = j0 + ni * 8 + (lid & 3) * 2;
                if (col > qA)     z[ni][0] = -CUDART_INF_F;
                if (col + 1 > qA) z[ni][1] = -CUDART_INF_F;
                if (col > qB)     z[ni][2] = -CUDART_INF_F;
                if (col + 1 > qB) z[ni][3] = -CUDART_INF_F;
            }
        }

        // row max (4 lanes share a row: xor 1, 2)
        float m0 = -CUDART_INF_F, m1 = -CUDART_INF_F;
#pragma unroll
        for (int ni = 0; ni < 8; ni++) {
            m0 = fmaxf(m0, fmaxf(z[ni][0], z[ni][1]));
            m1 = fmaxf(m1, fmaxf(z[ni][2], z[ni][3]));
        }
        m0 = fmaxf(m0, __shfl_xor_sync(0xffffffffu, m0, 1));
        m0 = fmaxf(m0, __shfl_xor_sync(0xffffffffu, m0, 2));
        m1 = fmaxf(m1, __shfl_xor_sync(0xffffffffu, m1, 1));
        m1 = fmaxf(m1, __shfl_xor_sync(0xffffffffu, m1, 2));

        const float mn0 = fmaxf(mi0, m0);
        const float mn1 = fmaxf(mi1, m1);
        const float al0 = exp2f(mi0 - mn0);
        const float al1 = exp2f(mi1 - mn1);
        mi0 = mn0; mi1 = mn1;

        // p = exp2(z - m), row sums, pack into hi/lo A fragments
        uint32_t pah[8][2], pal[8][2];
        float rs0 = 0.0f, rs1 = 0.0f;
#pragma unroll
        for (int ni = 0; ni < 8; ni++) {
            const float p0 = exp2f(z[ni][0] - mn0);
            const float p1 = exp2f(z[ni][1] - mn0);
            const float p2 = exp2f(z[ni][2] - mn1);
            const float p3 = exp2f(z[ni][3] - mn1);
            rs0 += p0 + p1;
            rs1 += p2 + p3;
            split2(p0, p1, pah[ni][0], pal[ni][0]);
            split2(p2, p3, pah[ni][1], pal[ni][1]);
        }
        rs0 += __shfl_xor_sync(0xffffffffu, rs0, 1);
        rs0 += __shfl_xor_sync(0xffffffffu, rs0, 2);
        rs1 += __shfl_xor_sync(0xffffffffu, rs1, 1);
        rs1 += __shfl_xor_sync(0xffffffffu, rs1, 2);
        li0 = li0 * al0 + rs0;
        li1 = li1 * al1 + rs1;

        // rescale O
#pragma unroll
        for (int ni = 0; ni < 8; ni++) {
            O[ni][0] *= al0; O[ni][1] *= al0;
            O[ni][2] *= al1; O[ni][3] *= al1;
        }

        // ---- PV ----
        const uint32_t vb = kvb + 2 * TILE_KV;
#pragma unroll
        for (int kc = 0; kc < 4; kc++) {
            uint32_t ah[4] = {pah[2*kc][0], pah[2*kc][1], pah[2*kc+1][0], pah[2*kc+1][1]};
            uint32_t al[4] = {pal[2*kc][0], pal[2*kc][1], pal[2*kc+1][0], pal[2*kc+1][1]};
#pragma unroll
            for (int ni = 0; ni < 8; ni++) {
                uint32_t vh[2], vl[2];
                const uint32_t vo = vb + (uint32_t)((kc * 16 + (lid & 15)) * AROWB + ni * 16);
                ldsm2t(vh, vo);
                ldsm2t(vl, vo + TILE_KV);
                mma16816(O[ni], ah, vh);
                mma16816(O[ni], al, vh);
                mma16816(O[ni], ah, vl);
            }
        }

        __syncthreads();
        if (t + 2 < ntiles) issue_kv(t + 2);
    }

    // ---- epilogue: normalize, split, store to [B*S, DM] ----
    const int b_ = bh >> 4;
    const int h_ = bh & (HH - 1);
    const int qA = q0 + w * 16 + (lid >> 2);
    const float inv0 = 1.0f / li0;
    const float inv1 = 1.0f / li1;
#pragma unroll
    for (int ni = 0; ni < 8; ni++) {
        const int dcol = h_ * DH + ni * 8 + (lid & 3) * 2;
        const size_t iA = (size_t)(b_ * SS + qA) * DM + dcol;
        const size_t iB = (size_t)(b_ * SS + qA + 8) * DM + dcol;
        uint32_t hv, lv;
        split2(O[ni][0] * inv0, O[ni][1] * inv0, hv, lv);
        *reinterpret_cast<uint32_t*>(aoh + iA) = hv;
        *reinterpret_cast<uint32_t*>(aol + iA) = lv;
        split2(O[ni][2] * inv1, O[ni][3] * inv1, hv, lv);
        *reinterpret_cast<uint32_t*>(aoh + iB) = hv;
        *reinterpret_cast<uint32_t*>(aol + iB) = lv;
    }
}

// ---------------------------------------------------------------------------
extern "C" void kernel_launch(void* const* d_in, const int* in_sizes, int n_in,
                              void* d_out, int out_size) {
    (void)in_sizes; (void)n_in; (void)out_size;
    const float* q    = (const float*)d_in[0];
    const float* k    = (const float*)d_in[1];
    const float* v    = (const float*)d_in[2];
    const float* wq_w = (const float*)d_in[3];
    const float* wq_b = (const float*)d_in[4];
    const float* wk_w = (const float*)d_in[5];
    const float* wk_b = (const float*)d_in[6];
    const float* wv_w = (const float*)d_in[7];
    const float* wv_b = (const float*)d_in[8];
    const float* wo_w = (const float*)d_in[9];
    const float* wo_b = (const float*)d_in[10];
    float* out = (float*)d_out;

    __nv_bfloat16 *xqh, *xql, *xkh, *xkl, *xvh, *xvl;
    __nv_bfloat16 *wqh, *wql, *wkh, *wkl, *wvh, *wvl, *woh, *wol;
    __nv_bfloat16 *Qh, *Ql, *Kh, *Kl, *Vh, *Vl, *aoh, *aol;
    cudaGetSymbolAddress((void**)&xqh, g_xq_hi); cudaGetSymbolAddress((void**)&xql, g_xq_lo);
    cudaGetSymbolAddress((void**)&xkh, g_xk_hi); cudaGetSymbolAddress((void**)&xkl, g_xk_lo);
    cudaGetSymbolAddress((void**)&xvh, g_xv_hi); cudaGetSymbolAddress((void**)&xvl, g_xv_lo);
    cudaGetSymbolAddress((void**)&wqh, g_wq_hi); cudaGetSymbolAddress((void**)&wql, g_wq_lo);
    cudaGetSymbolAddress((void**)&wkh, g_wk_hi); cudaGetSymbolAddress((void**)&wkl, g_wk_lo);
    cudaGetSymbolAddress((void**)&wvh, g_wv_hi); cudaGetSymbolAddress((void**)&wvl, g_wv_lo);
    cudaGetSymbolAddress((void**)&woh, g_wo_hi); cudaGetSymbolAddress((void**)&wol, g_wo_lo);
    cudaGetSymbolAddress((void**)&Qh, g_Qh); cudaGetSymbolAddress((void**)&Ql, g_Ql);
    cudaGetSymbolAddress((void**)&Kh, g_Kh); cudaGetSymbolAddress((void**)&Kl, g_Kl);
    cudaGetSymbolAddress((void**)&Vh, g_Vh); cudaGetSymbolAddress((void**)&Vl, g_Vl);
    cudaGetSymbolAddress((void**)&aoh, g_aoh); cudaGetSymbolAddress((void**)&aol, g_aol);

    cudaFuncSetAttribute(gemm_mma<true>,  cudaFuncAttributeMaxDynamicSharedMemorySize, GEMM_SMEM);
    cudaFuncSetAttribute(gemm_mma<false>, cudaFuncAttributeMaxDynamicSharedMemorySize, GEMM_SMEM);
    cudaFuncSetAttribute(attn_mma, cudaFuncAttributeMaxDynamicSharedMemorySize, ATTN_SMEM);

    const int NX = MROW * DM;   // 4M
    const int NW = DM * DM;     // 1M
    cvt_split<<<NX / 1024, 256>>>(q, xqh, xql, NX);
    cvt_split<<<NX / 1024, 256>>>(k, xkh, xkl, NX);
    cvt_split<<<NX / 1024, 256>>>(v, xvh, xvl, NX);
    cvt_split<<<NW / 1024, 256>>>(wq_w, wqh, wql, NW);
    cvt_split<<<NW / 1024, 256>>>(wk_w, wkh, wkl, NW);
    cvt_split<<<NW / 1024, 256>>>(wv_w, wvh, wvl, NW);
    cvt_split<<<NW / 1024, 256>>>(wo_w, woh, wol, NW);

    dim3 ggrid(DM / TN, MROW / TM);   // (8, 32)
    gemm_mma<true><<<ggrid, 256, GEMM_SMEM>>>(xqh, xql, wqh, wql, wq_b, nullptr, Qh, Ql);
    gemm_mma<true><<<ggrid, 256, GEMM_SMEM>>>(xkh, xkl, wkh, wkl, wk_b, nullptr, Kh, Kl);
    gemm_mma<true><<<ggrid, 256, GEMM_SMEM>>>(xvh, xvl, wvh, wvl, wv_b, nullptr, Vh, Vl);

    dim3 agrid(SS / 128, BB * HH);    // (16, 32)
    attn_mma<<<agrid, 256, ATTN_SMEM>>>(Qh, Ql, Kh, Kl, Vh, Vl, aoh, aol);

    gemm_mma<false><<<ggrid, 256, GEMM_SMEM>>>(aoh, aol, woh, wol, wo_b, out, nullptr, nullptr);
}

// round 6
// speedup vs baseline: 3.8848x; 1.0524x over previous
#include <cuda_runtime.h>
#include <cuda_bf16.h>
#include <math_constants.h>
#include <cstdint>

// Problem constants
constexpr int BB   = 2;
constexpr int SS   = 2048;
constexpr int DM   = 1024;
constexpr int HH   = 16;
constexpr int DH   = 64;
constexpr int MROW = BB * SS;   // 4096

// ---------------------------------------------------------------------------
// Scratch (device globals: allocation-free)
// ---------------------------------------------------------------------------
__device__ __nv_bfloat16 g_xq_hi[MROW * DM], g_xq_lo[MROW * DM];
__device__ __nv_bfloat16 g_xk_hi[MROW * DM], g_xk_lo[MROW * DM];
__device__ __nv_bfloat16 g_xv_hi[MROW * DM], g_xv_lo[MROW * DM];
__device__ __nv_bfloat16 g_wq_hi[DM * DM],  g_wq_lo[DM * DM];
__device__ __nv_bfloat16 g_wk_hi[DM * DM],  g_wk_lo[DM * DM];
__device__ __nv_bfloat16 g_wv_hi[DM * DM],  g_wv_lo[DM * DM];
__device__ __nv_bfloat16 g_wo_hi[DM * DM],  g_wo_lo[DM * DM];
__device__ __nv_bfloat16 g_Qh[BB*HH*SS*DH], g_Ql[BB*HH*SS*DH];
__device__ __nv_bfloat16 g_Kh[BB*HH*SS*DH], g_Kl[BB*HH*SS*DH];
__device__ __nv_bfloat16 g_Vh[BB*HH*SS*DH], g_Vl[BB*HH*SS*DH];
__device__ __nv_bfloat16 g_aoh[MROW * DM], g_aol[MROW * DM];

// ---------------------------------------------------------------------------
// PTX helpers
// ---------------------------------------------------------------------------
__device__ __forceinline__ uint32_t smem_u32(const void* p) {
    uint32_t a;
    asm("{ .reg .u64 t; cvta.to.shared.u64 t, %1; cvt.u32.u64 %0, t; }" : "=r"(a) : "l"(p));
    return a;
}
__device__ __forceinline__ void cp16(uint32_t saddr, const void* gaddr) {
    asm volatile("cp.async.cg.shared.global [%0], [%1], 16;" :: "r"(saddr), "l"(gaddr));
}
__device__ __forceinline__ void cp_commit() {
    asm volatile("cp.async.commit_group;" ::: "memory");
}
template <int N>
__device__ __forceinline__ void cp_wait() {
    asm volatile("cp.async.wait_group %0;" :: "n"(N) : "memory");
}
__device__ __forceinline__ void ldsm4(uint32_t* r, uint32_t addr) {
    asm volatile("ldmatrix.sync.aligned.m8n8.x4.shared.b16 {%0,%1,%2,%3}, [%4];"
                 : "=r"(r[0]), "=r"(r[1]), "=r"(r[2]), "=r"(r[3]) : "r"(addr));
}
__device__ __forceinline__ void ldsm2(uint32_t* r, uint32_t addr) {
    asm volatile("ldmatrix.sync.aligned.m8n8.x2.shared.b16 {%0,%1}, [%2];"
                 : "=r"(r[0]), "=r"(r[1]) : "r"(addr));
}
__device__ __forceinline__ void ldsm2t(uint32_t* r, uint32_t addr) {
    asm volatile("ldmatrix.sync.aligned.m8n8.x2.trans.shared.b16 {%0,%1}, [%2];"
                 : "=r"(r[0]), "=r"(r[1]) : "r"(addr));
}
__device__ __forceinline__ void mma16816(float* c, const uint32_t* a, const uint32_t* b) {
    asm volatile(
        "mma.sync.aligned.m16n8k16.row.col.f32.bf16.bf16.f32 "
        "{%0,%1,%2,%3}, {%4,%5,%6,%7}, {%8,%9}, {%0,%1,%2,%3};"
        : "+f"(c[0]), "+f"(c[1]), "+f"(c[2]), "+f"(c[3])
        : "r"(a[0]), "r"(a[1]), "r"(a[2]), "r"(a[3]), "r"(b[0]), "r"(b[1]));
}
__device__ __forceinline__ void split2(float a, float b, uint32_t& hi, uint32_t& lo) {
    __nv_bfloat16 ha = __float2bfloat16(a);
    __nv_bfloat16 hb = __float2bfloat16(b);
    __nv_bfloat162 hv; hv.x = ha; hv.y = hb;
    __nv_bfloat162 lv;
    lv.x = __float2bfloat16(a - __bfloat162float(ha));
    lv.y = __float2bfloat16(b - __bfloat162float(hb));
    hi = *reinterpret_cast<uint32_t*>(&hv);
    lo = *reinterpret_cast<uint32_t*>(&lv);
}

// ---------------------------------------------------------------------------
// Fused fp32 -> bf16 hi/lo conversion for all 7 tensors in one launch.
// ---------------------------------------------------------------------------
struct CvtArgs {
    const float* src[7];
    __nv_bfloat16* hi[7];
    __nv_bfloat16* lo[7];
    int nblk[7];   // blocks per segment (each block = 1024 elems)
    int cum[8];    // cumulative block offsets
};

__global__ void __launch_bounds__(256) cvt_all(CvtArgs a) {
    int blk = blockIdx.x;
    int seg = 0;
#pragma unroll
    for (int s = 0; s < 7; s++)
        if (blk >= a.cum[s + 1]) seg = s + 1;
    const int i = (blk - a.cum[seg]) * 1024 + threadIdx.x * 4;
    const float* src = a.src[seg];
    float4 v = *reinterpret_cast<const float4*>(src + i);
    uint32_t h0, l0, h1, l1;
    split2(v.x, v.y, h0, l0);
    split2(v.z, v.w, h1, l1);
    reinterpret_cast<uint32_t*>(a.hi[seg] + i)[0] = h0;
    reinterpret_cast<uint32_t*>(a.hi[seg] + i)[1] = h1;
    reinterpret_cast<uint32_t*>(a.lo[seg] + i)[0] = l0;
    reinterpret_cast<uint32_t*>(a.lo[seg] + i)[1] = l1;
}

// ---------------------------------------------------------------------------
// mma.sync GEMM: out = A @ B^T + bias.  3-term bf16 hi/lo split, fp32 accum.
// CTA 128x128, warp 64x32, K-stage 32, 2 CTAs/SM, cp.async double buffer.
// FUSE3: blockIdx.z selects one of 3 input sets (QKV projections), writes
//        bf16 hi/lo scattered to [B,H,S,Dh].  Else fp32 [M,N] (out proj).
// ---------------------------------------------------------------------------
constexpr int TKS   = 32;                     // K per stage
constexpr int NSTG  = DM / TKS;               // 32
constexpr int ROWB  = 80;                     // 32 bf16 = 64B + 16B pad
constexpr int TILE_B = 128 * ROWB;            // 10240
constexpr int BUF_B  = 4 * TILE_B;            // 40960
constexpr int GEMM_SMEM = 2 * BUF_B;          // 81920

struct Gemm3Args {
    const __nv_bfloat16 *Ahi[3], *Alo[3], *Bhi[3], *Blo[3];
    const float* bias[3];
    __nv_bfloat16 *outh[3], *outl[3];
};

template <bool FUSE3>
__global__ void __launch_bounds__(256, 2) gemm_mma(Gemm3Args ga,
                                                   float* __restrict__ out_f32) {
    extern __shared__ __align__(128) char smem[];
    const uint32_t sb = smem_u32(smem);
    const int tid = threadIdx.x;
    const int wid = tid >> 5;
    const int lid = tid & 31;
    const int wm  = wid >> 2;
    const int wn  = wid & 3;
    const int m0  = blockIdx.y * 128;
    const int n0  = blockIdx.x * 128;
    const int z   = FUSE3 ? blockIdx.z : 0;

    const __nv_bfloat16* gsrc[4] = {ga.Ahi[z], ga.Alo[z], ga.Bhi[z], ga.Blo[z]};
    const int gbase[4] = {m0, m0, n0, n0};

    auto issue_stage = [&](int s) {
        const uint32_t sbase = sb + (s & 1) * BUF_B;
        const int k0 = s * TKS;
#pragma unroll
        for (int t = 0; t < 4; t++) {
            const __nv_bfloat16* src = gsrc[t];
            const int rb = gbase[t];
#pragma unroll
            for (int i = 0; i < 2; i++) {
                const int idx = tid + i * 256;      // 0..511
                const int row = idx >> 2;
                const int c   = idx & 3;
                cp16(sbase + t * TILE_B + row * ROWB + c * 16,
                     src + (size_t)(rb + row) * DM + k0 + c * 8);
            }
        }
        cp_commit();
    };

    issue_stage(0);
    issue_stage(1);

    float acc[4][4][4] = {};

    const int aRowIn = (lid & 7) + 8 * ((lid >> 3) & 1);
    const int aKc    = ((lid >> 4) & 1) * 16;
    // ldsm4 B: lanes 0-7 -> ni rows kb; 8-15 -> ni rows kb+16; 16-23 -> ni+1 rows kb; 24-31 -> +16
    const int bRow   = lid & 7;
    const int bPair  = (lid >> 4) & 1;          // which n-tile of the pair
    const int bHalf  = (lid >> 3) & 1;          // k half 16B

    for (int s = 0; s < NSTG; s++) {
        if (s == NSTG - 1) cp_wait<0>(); else cp_wait<1>();
        __syncthreads();

        const uint32_t sbase = sb + (s & 1) * BUF_B;
        const uint32_t Ah = sbase;
        const uint32_t Al = sbase + TILE_B;
        const uint32_t Bh = sbase + 2 * TILE_B;
        const uint32_t Bl = sbase + 3 * TILE_B;

#pragma unroll
        for (int ks = 0; ks < 2; ks++) {
            const int kb = ks * 32;   // 16 bf16 = 32B
            uint32_t bh[4][2], bl[4][2];
#pragma unroll
            for (int np = 0; np < 2; np++) {      // pairs (ni=2np, 2np+1)
                const uint32_t boff = (uint32_t)(
                    (wn * 32 + (np * 2 + bPair) * 8 + bRow) * ROWB + kb + bHalf * 16);
                uint32_t r4[4];
                ldsm4(r4, Bh + boff);
                bh[np*2][0] = r4[0]; bh[np*2][1] = r4[1];
                bh[np*2+1][0] = r4[2]; bh[np*2+1][1] = r4[3];
                ldsm4(r4, Bl + boff);
                bl[np*2][0] = r4[0]; bl[np*2][1] = r4[1];
                bl[np*2+1][0] = r4[2]; bl[np*2+1][1] = r4[3];
            }
#pragma unroll
            for (int mi = 0; mi < 4; mi++) {
                uint32_t ah[4], al[4];
                const uint32_t aoff = (uint32_t)((wm * 64 + mi * 16 + aRowIn) * ROWB + kb + aKc);
                ldsm4(ah, Ah + aoff);
                ldsm4(al, Al + aoff);
#pragma unroll
                for (int ni = 0; ni < 4; ni++) {
                    mma16816(acc[mi][ni], ah, bh[ni]);
                    mma16816(acc[mi][ni], al, bh[ni]);
                    mma16816(acc[mi][ni], ah, bl[ni]);
                }
            }
        }
        __syncthreads();
        if (s + 2 < NSTG) issue_stage(s + 2);
    }

    // Epilogue
    const int qr = lid >> 2;
    const int qc = (lid & 3) * 2;
    const float* bias = ga.bias[z];
#pragma unroll
    for (int mi = 0; mi < 4; mi++) {
#pragma unroll
        for (int ni = 0; ni < 4; ni++) {
            const int n = n0 + wn * 32 + ni * 8 + qc;
            const float2 bv = *reinterpret_cast<const float2*>(bias + n);
#pragma unroll
            for (int half = 0; half < 2; half++) {
                const int m = m0 + wm * 64 + mi * 16 + qr + half * 8;
                const float vx = acc[mi][ni][half * 2 + 0] + bv.x;
                const float vy = acc[mi][ni][half * 2 + 1] + bv.y;
                if (FUSE3) {
                    const int b_ = m >> 11;
                    const int s_ = m & (SS - 1);
                    const int h_ = n >> 6;
                    const int d_ = n & (DH - 1);
                    const size_t o = (((size_t)b_ * HH + h_) * SS + s_) * DH + d_;
                    uint32_t hv, lv;
                    split2(vx, vy, hv, lv);
                    *reinterpret_cast<uint32_t*>(ga.outh[z] + o) = hv;
                    *reinterpret_cast<uint32_t*>(ga.outl[z] + o) = lv;
                } else {
                    float2 v; v.x = vx; v.y = vy;
                    *reinterpret_cast<float2*>(out_f32 + (size_t)m * DM + n) = v;
                }
            }
        }
    }
}

// ---------------------------------------------------------------------------
// mma.sync causal flash attention (unchanged from round 5).
// ---------------------------------------------------------------------------
constexpr int AROWB   = 144;
constexpr int TILE_KV = 64 * AROWB;            // 9216
constexpr int STAGE_B = 4 * TILE_KV;           // 36864
constexpr int QOFF    = 2 * STAGE_B;           // 73728
constexpr int QTILE   = 128 * AROWB;           // 18432
constexpr int ATTN_SMEM = QOFF + 2 * QTILE;    // 110592

__global__ void __launch_bounds__(256, 1) attn_mma(const __nv_bfloat16* __restrict__ Qh_g,
                                                   const __nv_bfloat16* __restrict__ Ql_g,
                                                   const __nv_bfloat16* __restrict__ Kh_g,
                                                   const __nv_bfloat16* __restrict__ Kl_g,
                                                   const __nv_bfloat16* __restrict__ Vh_g,
                                                   const __nv_bfloat16* __restrict__ Vl_g,
                                                   __nv_bfloat16* __restrict__ aoh,
                                                   __nv_bfloat16* __restrict__ aol) {
    extern __shared__ __align__(128) char smem[];
    const uint32_t sb = smem_u32(smem);
    const int tid = threadIdx.x;
    const int w   = tid >> 5;
    const int lid = tid & 31;

    const int q0 = blockIdx.x * 128;
    const int bh = blockIdx.y;
    const size_t bhbase = (size_t)bh * SS;

    const int ntiles = (q0 >> 6) + 2;

    auto issue_kv = [&](int t) {
        const int j0 = t * 64;
        const uint32_t sbase = sb + (t & 1) * STAGE_B;
        const __nv_bfloat16* srcs[4] = {Kh_g, Kl_g, Vh_g, Vl_g};
#pragma unroll
        for (int a = 0; a < 4; a++) {
#pragma unroll
            for (int i = 0; i < 2; i++) {
                const int idx = tid + i * 256;
                const int row = idx >> 3, c = idx & 7;
                cp16(sbase + a * TILE_KV + row * AROWB + c * 16,
                     srcs[a] + (bhbase + j0 + row) * DH + c * 8);
            }
        }
        cp_commit();
    };

    {
        const __nv_bfloat16* qs[2] = {Qh_g, Ql_g};
#pragma unroll
        for (int a = 0; a < 2; a++) {
#pragma unroll
            for (int i = 0; i < 4; i++) {
                const int idx = tid + i * 256;
                const int row = idx >> 3, c = idx & 7;
                cp16(sb + QOFF + a * QTILE + row * AROWB + c * 16,
                     qs[a] + (bhbase + q0 + row) * DH + c * 8);
            }
        }
        issue_kv(0);
    }
    if (ntiles > 1) issue_kv(1);

    const int aRowIn = (lid & 7) + 8 * ((lid >> 3) & 1);
    const int aKc    = ((lid >> 4) & 1) * 16;

    uint32_t qh[4][4], ql[4][4];
    float O[8][4] = {};
    float mi0 = -CUDART_INF_F, mi1 = -CUDART_INF_F;
    float li0 = 0.0f, li1 = 0.0f;
    const float sc_log2e = 0.125f * 1.4426950408889634f;

    for (int t = 0; t < ntiles; t++) {
        if (t == ntiles - 1) cp_wait<0>(); else cp_wait<1>();
        __syncthreads();

        if (t == 0) {
            const uint32_t qb = sb + QOFF + (uint32_t)((w * 16 + aRowIn) * AROWB + aKc);
#pragma unroll
            for (int kc = 0; kc < 4; kc++) {
                ldsm4(qh[kc], qb + kc * 32);
                ldsm4(ql[kc], qb + QTILE + kc * 32);
            }
        }

        const uint32_t kvb = sb + (t & 1) * STAGE_B;
        const int j0 = t * 64;

        float z[8][4] = {};
#pragma unroll
        for (int kc = 0; kc < 4; kc++) {
#pragma unroll
            for (int ni = 0; ni < 8; ni++) {
                uint32_t kh[2], kl[2];
                const uint32_t ko = kvb + (uint32_t)((ni * 8 + (lid & 7)) * AROWB
                                                     + kc * 32 + ((lid >> 3) & 1) * 16);
                ldsm2(kh, ko);
                ldsm2(kl, ko + TILE_KV);
                mma16816(z[ni], qh[kc], kh);
                mma16816(z[ni], ql[kc], kh);
                mma16816(z[ni], qh[kc], kl);
            }
        }

        const int qA = q0 + w * 16 + (lid >> 2);
        const int qB = qA + 8;
        const bool domask = (j0 + 63 > q0 + w * 16);
#pragma unroll
        for (int ni = 0; ni < 8; ni++) {
#pragma unroll
            for (int c = 0; c < 4; c++) z[ni][c] *= sc_log2e;
            if (domask) {
                const int col = j0 + ni * 8 + (lid & 3) * 2;
                if (col > qA)     z[ni][0] = -CUDART_INF_F;
                if (col + 1 > qA) z[ni][1] = -CUDART_INF_F;
                if (col > qB)     z[ni][2] = -CUDART_INF_F;
                if (col + 1 > qB) z[ni][3] = -CUDART_INF_F;
            }
        }

        float m0 = -CUDART_INF_F, m1 = -CUDART_INF_F;
#pragma unroll
        for (int ni = 0; ni < 8; ni++) {
            m0 = fmaxf(m0, fmaxf(z[ni][0], z[ni][1]));
            m1 = fmaxf(m1, fmaxf(z[ni][2], z[ni][3]));
        }
        m0 = fmaxf(m0, __shfl_xor_sync(0xffffffffu, m0, 1));
        m0 = fmaxf(m0, __shfl_xor_sync(0xffffffffu, m0, 2));
        m1 = fmaxf(m1, __shfl_xor_sync(0xffffffffu, m1, 1));
        m1 = fmaxf(m1, __shfl_xor_sync(0xffffffffu, m1, 2));

        const float mn0 = fmaxf(mi0, m0);
        const float mn1 = fmaxf(mi1, m1);
        const float al0 = exp2f(mi0 - mn0);
        const float al1 = exp2f(mi1 - mn1);
        mi0 = mn0; mi1 = mn1;

        uint32_t pah[8][2], pal[8][2];
        float rs0 = 0.0f, rs1 = 0.0f;
#pragma unroll
        for (int ni = 0; ni < 8; ni++) {
            const float p0 = exp2f(z[ni][0] - mn0);
            const float p1 = exp2f(z[ni][1] - mn0);
            const float p2 = exp2f(z[ni][2] - mn1);
            const float p3 = exp2f(z[ni][3] - mn1);
            rs0 += p0 + p1;
            rs1 += p2 + p3;
            split2(p0, p1, pah[ni][0], pal[ni][0]);
            split2(p2, p3, pah[ni][1], pal[ni][1]);
        }
        rs0 += __shfl_xor_sync(0xffffffffu, rs0, 1);
        rs0 += __shfl_xor_sync(0xffffffffu, rs0, 2);
        rs1 += __shfl_xor_sync(0xffffffffu, rs1, 1);
        rs1 += __shfl_xor_sync(0xffffffffu, rs1, 2);
        li0 = li0 * al0 + rs0;
        li1 = li1 * al1 + rs1;

#pragma unroll
        for (int ni = 0; ni < 8; ni++) {
            O[ni][0] *= al0; O[ni][1] *= al0;
            O[ni][2] *= al1; O[ni][3] *= al1;
        }

        const uint32_t vb = kvb + 2 * TILE_KV;
#pragma unroll
        for (int kc = 0; kc < 4; kc++) {
            uint32_t ah[4] = {pah[2*kc][0], pah[2*kc][1], pah[2*kc+1][0], pah[2*kc+1][1]};
            uint32_t al[4] = {pal[2*kc][0], pal[2*kc][1], pal[2*kc+1][0], pal[2*kc+1][1]};
#pragma unroll
            for (int ni = 0; ni < 8; ni++) {
                uint32_t vh[2], vl[2];
                const uint32_t vo = vb + (uint32_t)((kc * 16 + (lid & 15)) * AROWB + ni * 16);
                ldsm2t(vh, vo);
                ldsm2t(vl, vo + TILE_KV);
                mma16816(O[ni], ah, vh);
                mma16816(O[ni], al, vh);
                mma16816(O[ni], ah, vl);
            }
        }

        __syncthreads();
        if (t + 2 < ntiles) issue_kv(t + 2);
    }

    const int b_ = bh >> 4;
    const int h_ = bh & (HH - 1);
    const int qA = q0 + w * 16 + (lid >> 2);
    const float inv0 = 1.0f / li0;
    const float inv1 = 1.0f / li1;
#pragma unroll
    for (int ni = 0; ni < 8; ni++) {
        const int dcol = h_ * DH + ni * 8 + (lid & 3) * 2;
        const size_t iA = (size_t)(b_ * SS + qA) * DM + dcol;
        const size_t iB = (size_t)(b_ * SS + qA + 8) * DM + dcol;
        uint32_t hv, lv;
        split2(O[ni][0] * inv0, O[ni][1] * inv0, hv, lv);
        *reinterpret_cast<uint32_t*>(aoh + iA) = hv;
        *reinterpret_cast<uint32_t*>(aol + iA) = lv;
        split2(O[ni][2] * inv1, O[ni][3] * inv1, hv, lv);
        *reinterpret_cast<uint32_t*>(aoh + iB) = hv;
        *reinterpret_cast<uint32_t*>(aol + iB) = lv;
    }
}

// ---------------------------------------------------------------------------
extern "C" void kernel_launch(void* const* d_in, const int* in_sizes, int n_in,
                              void* d_out, int out_size) {
    (void)in_sizes; (void)n_in; (void)out_size;
    const float* q    = (const float*)d_in[0];
    const float* k    = (const float*)d_in[1];
    const float* v    = (const float*)d_in[2];
    const float* wq_w = (const float*)d_in[3];
    const float* wq_b = (const float*)d_in[4];
    const float* wk_w = (const float*)d_in[5];
    const float* wk_b = (const float*)d_in[6];
    const float* wv_w = (const float*)d_in[7];
    const float* wv_b = (const float*)d_in[8];
    const float* wo_w = (const float*)d_in[9];
    const float* wo_b = (const float*)d_in[10];
    float* out = (float*)d_out;

    __nv_bfloat16 *xqh, *xql, *xkh, *xkl, *xvh, *xvl;
    __nv_bfloat16 *wqh, *wql, *wkh, *wkl, *wvh, *wvl, *woh, *wol;
    __nv_bfloat16 *Qh, *Ql, *Kh, *Kl, *Vh, *Vl, *aoh, *aol;
    cudaGetSymbolAddress((void**)&xqh, g_xq_hi); cudaGetSymbolAddress((void**)&xql, g_xq_lo);
    cudaGetSymbolAddress((void**)&xkh, g_xk_hi); cudaGetSymbolAddress((void**)&xkl, g_xk_lo);
    cudaGetSymbolAddress((void**)&xvh, g_xv_hi); cudaGetSymbolAddress((void**)&xvl, g_xv_lo);
    cudaGetSymbolAddress((void**)&wqh, g_wq_hi); cudaGetSymbolAddress((void**)&wql, g_wq_lo);
    cudaGetSymbolAddress((void**)&wkh, g_wk_hi); cudaGetSymbolAddress((void**)&wkl, g_wk_lo);
    cudaGetSymbolAddress((void**)&wvh, g_wv_hi); cudaGetSymbolAddress((void**)&wvl, g_wv_lo);
    cudaGetSymbolAddress((void**)&woh, g_wo_hi); cudaGetSymbolAddress((void**)&wol, g_wo_lo);
    cudaGetSymbolAddress((void**)&Qh, g_Qh); cudaGetSymbolAddress((void**)&Ql, g_Ql);
    cudaGetSymbolAddress((void**)&Kh, g_Kh); cudaGetSymbolAddress((void**)&Kl, g_Kl);
    cudaGetSymbolAddress((void**)&Vh, g_Vh); cudaGetSymbolAddress((void**)&Vl, g_Vl);
    cudaGetSymbolAddress((void**)&aoh, g_aoh); cudaGetSymbolAddress((void**)&aol, g_aol);

    cudaFuncSetAttribute(gemm_mma<true>,  cudaFuncAttributeMaxDynamicSharedMemorySize, GEMM_SMEM);
    cudaFuncSetAttribute(gemm_mma<false>, cudaFuncAttributeMaxDynamicSharedMemorySize, GEMM_SMEM);
    cudaFuncSetAttribute(attn_mma, cudaFuncAttributeMaxDynamicSharedMemorySize, ATTN_SMEM);

    // --- fused convert: q,k,v (4096 blocks each), 4 weights (1024 blocks each) ---
    CvtArgs ca;
    const float* srcs[7] = {q, k, v, wq_w, wk_w, wv_w, wo_w};
    __nv_bfloat16* his[7] = {xqh, xkh, xvh, wqh, wkh, wvh, woh};
    __nv_bfloat16* los[7] = {xql, xkl, xvl, wql, wkl, wvl, wol};
    int cum = 0;
    for (int s = 0; s < 7; s++) {
        ca.src[s] = srcs[s]; ca.hi[s] = his[s]; ca.lo[s] = los[s];
        ca.nblk[s] = (s < 3) ? (MROW * DM / 1024) : (DM * DM / 1024);
        ca.cum[s] = cum; cum += ca.nblk[s];
    }
    ca.cum[7] = cum;
    cvt_all<<<cum, 256>>>(ca);

    // --- fused QKV projections ---
    Gemm3Args g3;
    g3.Ahi[0] = xqh; g3.Alo[0] = xql; g3.Bhi[0] = wqh; g3.Blo[0] = wql;
    g3.Ahi[1] = xkh; g3.Alo[1] = xkl; g3.Bhi[1] = wkh; g3.Blo[1] = wkl;
    g3.Ahi[2] = xvh; g3.Alo[2] = xvl; g3.Bhi[2] = wvh; g3.Blo[2] = wvl;
    g3.bias[0] = wq_b; g3.bias[1] = wk_b; g3.bias[2] = wv_b;
    g3.outh[0] = Qh; g3.outl[0] = Ql;
    g3.outh[1] = Kh; g3.outl[1] = Kl;
    g3.outh[2] = Vh; g3.outl[2] = Vl;
    dim3 ggrid3(DM / 128, MROW / 128, 3);   // (8, 32, 3)
    gemm_mma<true><<<ggrid3, 256, GEMM_SMEM>>>(g3, nullptr);

    // --- attention ---
    dim3 agrid(SS / 128, BB * HH);          // (16, 32)
    attn_mma<<<agrid, 256, ATTN_SMEM>>>(Qh, Ql, Kh, Kl, Vh, Vl, aoh, aol);

    // --- output projection ---
    Gemm3Args go = {};
    go.Ahi[0] = aoh; go.Alo[0] = aol; go.Bhi[0] = woh; go.Blo[0] = wol;
    go.bias[0] = wo_b;
    dim3 ggrid(DM / 128, MROW / 128, 1);    // (8, 32, 1)
    gemm_mma<false><<<ggrid, 256, GEMM_SMEM>>>(go, out);
}